// round 17
// baseline (speedup 1.0000x reference)
#include <cuda_runtime.h>
#include <cuda_fp16.h>
#include <mma.h>
#include <math.h>
#include <stdint.h>

using namespace nvcuda;

#define NJ 24
#define POSE_STRIDE (NJ * 3)
#define GROW 12
#define MAX_B 1024
#define MAX_ROWS (4 * MAX_B)
#define MAX_VPAD 8192
#define KREAL 97                  // 96 G-cols + 1 trans col
#define KTOT 128                  // padded K (single fp16 pass)
#define KC 64                     // K per smem chunk
#define NCHUNK (KTOT / KC)        // 2
#define LDS 72                    // SMEM leading dim (fp16), 144B rows

__constant__ int c_par[NJ] = {-1, 0, 0, 0, 1, 2, 3, 4, 5, 6, 7, 8, 9, 9, 9,
                              12, 13, 14, 16, 17, 18, 19, 20, 21};
__constant__ int c_lvl[NJ] = {0, 1, 1, 1, 2, 2, 2, 3, 3, 3, 4, 4, 4, 4, 4,
                              5, 5, 5, 6, 6, 7, 7, 8, 8};

// scratch (no allocation)
__device__ __align__(256) __half g_A[(size_t)MAX_ROWS * KTOT];
__device__ __align__(256) __half g_Bm[(size_t)MAX_VPAD * KTOT];

__device__ __forceinline__ uint32_t smem_u32(const void* p) {
    uint32_t a;
    asm("{ .reg .u64 t; cvta.to.shared.u64 t, %1; cvt.u32.u64 %0, t; }"
        : "=r"(a) : "l"(p));
    return a;
}
__device__ __forceinline__ void cp_async16(uint32_t dst, const void* src) {
    asm volatile("cp.async.cg.shared.global [%0], [%1], 16;"
                 :: "r"(dst), "l"(src) : "memory");
}
__device__ __forceinline__ void cp_async_wait_all() {
    asm volatile("cp.async.commit_group;\n\tcp.async.wait_group 0;" ::: "memory");
}

// ---------------------------------------------------------------------------
// prep_kernel (fused): blocks [0, pb_blocks) build B rows (32 verts/block);
// blocks [pb_blocks, ...) run FK for 4 batches each + emit A rows (fp16).
// A row layout is x-major: row = x*SB + b  (SB = padded batch count).
// ---------------------------------------------------------------------------
#define PB_VPB 32

__global__ __launch_bounds__(256)
void prep_kernel(const float* __restrict__ pose,
                 const float* __restrict__ J_hat,
                 const float* __restrict__ trans,
                 const float* __restrict__ T_hat,
                 const float* __restrict__ W,
                 int B, int V, int vpad, int SB, int pb_blocks) {
    int tid = threadIdx.x;

    if ((int)blockIdx.x < pb_blocks) {
        // ---- B operand
        int v_off = tid >> 7;
        int k = tid & 127;
        int j = k >> 2, y = k & 3;
        #pragma unroll
        for (int it = 0; it < PB_VPB / 2; it++) {
            int v = blockIdx.x * PB_VPB + it * 2 + v_off;
            if (v >= vpad) break;
            float val = 0.0f;
            if (v < V) {
                if (k < 96) {
                    float vh = (y < 3) ? T_hat[v * 3 + y] : 1.0f;
                    val = W[(size_t)v * NJ + j] * vh;
                } else if (k == KREAL - 1) {
                    val = 1.0f;
                }
            }
            g_Bm[(size_t)v * KTOT + k] = __float2half(val);
        }
        return;
    }

    // ---- FK for 4 batches + A emission
    int blk = blockIdx.x - pb_blocks;
    __shared__ float Gs[4][NJ][GROW];
    int lb = tid / NJ;
    int jj = tid - lb * NJ;
    bool jact = (tid < 96);
    int b = blk * 4 + lb;
    bool bok = jact && (b < B);

    if (bok) {
        float rx = pose[b * POSE_STRIDE + jj * 3 + 0];
        float ry = pose[b * POSE_STRIDE + jj * 3 + 1];
        float rz = pose[b * POSE_STRIDE + jj * 3 + 2];
        float theta = sqrtf(rx * rx + ry * ry + rz * rz) + 1e-8f;
        float inv = 1.0f / theta;
        float ux = rx * inv, uy = ry * inv, uz = rz * inv;
        float c = cosf(theta), s = sinf(theta), ic = 1.0f - c;
        int p = c_par[jj];
        float jx = J_hat[jj * 3 + 0], jy = J_hat[jj * 3 + 1], jz = J_hat[jj * 3 + 2];
        if (p >= 0) { jx -= J_hat[p*3+0]; jy -= J_hat[p*3+1]; jz -= J_hat[p*3+2]; }
        float* G = Gs[lb][jj];
        G[0] = c + ic*ux*ux;  G[1] = ic*ux*uy - s*uz; G[2]  = ic*ux*uz + s*uy; G[3]  = jx;
        G[4] = ic*uy*ux+s*uz; G[5] = c + ic*uy*uy;    G[6]  = ic*uy*uz - s*ux; G[7]  = jy;
        G[8] = ic*uz*ux-s*uy; G[9] = ic*uz*uy + s*ux; G[10] = c + ic*uz*uz;    G[11] = jz;
    }
    __syncthreads();

    int mylvl = jact ? c_lvl[jj] : -1;
    int myp = jact ? c_par[jj] : 0;
    #pragma unroll
    for (int lv = 1; lv <= 8; lv++) {
        float tmp[GROW];
        bool act = bok && (mylvl == lv);
        if (act) {
            const float* P = Gs[lb][myp];
            const float* L = Gs[lb][jj];
            #pragma unroll
            for (int x = 0; x < 3; x++) {
                float p0 = P[x*4+0], p1 = P[x*4+1], p2 = P[x*4+2], p3 = P[x*4+3];
                tmp[x*4+0] = p0*L[0] + p1*L[4] + p2*L[8];
                tmp[x*4+1] = p0*L[1] + p1*L[5] + p2*L[9];
                tmp[x*4+2] = p0*L[2] + p1*L[6] + p2*L[10];
                tmp[x*4+3] = p0*L[3] + p1*L[7] + p2*L[11] + p3;
            }
        }
        __syncthreads();
        if (act) {
            #pragma unroll
            for (int k = 0; k < GROW; k++) Gs[lb][jj][k] = tmp[k];
        }
        __syncthreads();
    }

    if (bok) {
        float jx = J_hat[jj*3+0], jy = J_hat[jj*3+1], jz = J_hat[jj*3+2];
        float* G = Gs[lb][jj];
        G[3]  -= G[0]*jx + G[1]*jy + G[2]*jz;
        G[7]  -= G[4]*jx + G[5]*jy + G[6]*jz;
        G[11] -= G[8]*jx + G[9]*jy + G[10]*jz;
    }
    __syncthreads();

    // emit: 4 batches x 3 rows x 128 cols; row = x*SB + b (x-major)
    #pragma unroll
    for (int it = 0; it < 6; it++) {
        int idx = it * 256 + tid;        // 0..1535
        int k = idx & 127;
        int rl = idx >> 7;               // 0..11
        int elb = rl / 3;
        int x = rl - elb * 3;
        int eb = blk * 4 + elb;
        if (eb >= SB) continue;
        float val = 0.0f;
        if (eb < B) {
            if (k < 96) {
                val = Gs[elb][k >> 2][x * 4 + (k & 3)];
            } else if (k == KREAL - 1) {
                val = trans[eb * 3 + x];
            }
        }
        g_A[(size_t)(x * SB + eb) * KTOT + k] = __float2half(val);
    }
}

// ---------------------------------------------------------------------------
// GEMM via wmma fp16, x-major rows: each 128-row tile has constant x and 128
// consecutive batches -> fully affine epilogue (no div, hoisted guards).
// ---------------------------------------------------------------------------
#define LDC 68

__global__ __launch_bounds__(256)
void gemm_kernel(float* __restrict__ out, int V, int B, int SB) {
    __shared__ __align__(16) char smbuf[2 * 128 * LDS * 2];  // 36.9 KB
    __half* sA = reinterpret_cast<__half*>(smbuf);
    __half* sB = sA + 128 * LDS;
    float* sepi = reinterpret_cast<float*>(smbuf);

    int tid = threadIdx.x;
    int warp = tid >> 5;
    int wr = warp >> 1;
    int wc = warp & 1;
    int r0 = blockIdx.x * 128;
    int v0 = blockIdx.y * 128;
    int xsec = r0 / SB;                  // constant per CTA (SB % 128 == 0)
    int b0 = r0 - xsec * SB;

    wmma::fragment<wmma::accumulator, 16, 16, 16, float> acc[2][4];
    #pragma unroll
    for (int i = 0; i < 2; i++)
        #pragma unroll
        for (int j = 0; j < 4; j++)
            wmma::fill_fragment(acc[i][j], 0.0f);

    // hoisted staging pointers: 256 threads cover 32 rows x 8 segs per step
    int srow = tid >> 3, seg = tid & 7;
    const __half* gA0 = g_A + (size_t)(r0 + srow) * KTOT + seg * 8;
    const __half* gB0 = g_Bm + (size_t)(v0 + srow) * KTOT + seg * 8;
    uint32_t sA32 = smem_u32(sA) + (uint32_t)(srow * LDS + seg * 8) * 2;
    uint32_t sB32 = smem_u32(sB) + (uint32_t)(srow * LDS + seg * 8) * 2;

    const __half* sAw = sA + (wr * 32) * LDS;   // warp A base
    const __half* sBw = sB + (wc * 64) * LDS;   // warp B base

    for (int c = 0; c < NCHUNK; c++) {
        const __half* ga = gA0 + c * KC;
        const __half* gb = gB0 + c * KC;
        #pragma unroll
        for (int p = 0; p < 4; p++) {
            cp_async16(sA32 + (uint32_t)(p * 32 * LDS * 2), ga + (size_t)p * 32 * KTOT);
            cp_async16(sB32 + (uint32_t)(p * 32 * LDS * 2), gb + (size_t)p * 32 * KTOT);
        }
        cp_async_wait_all();
        __syncthreads();

        #pragma unroll
        for (int ks = 0; ks < KC / 16; ks++) {
            int kk = ks * 16;
            wmma::fragment<wmma::matrix_a, 16, 16, 16, __half, wmma::row_major> af[2];
            wmma::fragment<wmma::matrix_b, 16, 16, 16, __half, wmma::col_major> bf[4];
            #pragma unroll
            for (int i = 0; i < 2; i++)
                wmma::load_matrix_sync(af[i], sAw + i * 16 * LDS + kk, LDS);
            #pragma unroll
            for (int j = 0; j < 4; j++)
                wmma::load_matrix_sync(bf[j], sBw + j * 16 * LDS + kk, LDS);
            #pragma unroll
            for (int i = 0; i < 2; i++)
                #pragma unroll
                for (int j = 0; j < 4; j++)
                    wmma::mma_sync(acc[i][j], af[i], bf[j], acc[i][j]);
        }
        __syncthreads();
    }

    // Epilogue: two 64-col passes; affine addressing, hoisted guards.
    int col = tid & 63;                  // 0..63 within pass
    int rbase = tid >> 6;                // 0..3, rows rbase, rbase+4, ...
    int nrow = B - b0;                   // valid rows in this tile (<=128)
    for (int p = 0; p < 2; p++) {
        __syncthreads();
        if (wc == p) {
            #pragma unroll
            for (int i = 0; i < 2; i++)
                #pragma unroll
                for (int j = 0; j < 4; j++)
                    wmma::store_matrix_sync(sepi + (wr * 32 + i * 16) * LDC + j * 16,
                                            acc[i][j], LDC, wmma::mem_row_major);
        }
        __syncthreads();

        int v = v0 + p * 64 + col;
        if (v < V) {
            const float* sp = sepi + rbase * LDC + col;
            float* gp = out + xsec + 3 * ((size_t)(b0 + rbase) * V + v);
            size_t gstep = (size_t)4 * 3 * V;
            #pragma unroll 8
            for (int i = 0; i < 32; i++) {
                int row = rbase + i * 4;
                if (row < nrow) gp[0] = sp[0];
                sp += 4 * LDC;
                gp += gstep;
            }
        }
    }
}

// ---------------------------------------------------------------------------
// Launch: pure kernel launches only (graph-capture safe).
// ---------------------------------------------------------------------------
extern "C" void kernel_launch(void* const* d_in, const int* in_sizes, int n_in,
                              void* d_out, int out_size) {
    const float* T_hat   = (const float*)d_in[0];   // (V,3)
    const float* J_hat   = (const float*)d_in[1];   // (24,3)
    const float* weights = (const float*)d_in[2];   // (V,24)
    const float* pose    = (const float*)d_in[3];   // (B,72)
    const float* trans   = (const float*)d_in[4];   // (B,3)
    float* out = (float*)d_out;

    int V = in_sizes[0] / 3;
    int B = in_sizes[3] / POSE_STRIDE;
    if (B > MAX_B) B = MAX_B;

    int SB = ((B + 127) / 128) * 128;               // 512 for B=512
    int rows_pad = 3 * SB;                          // 1536
    int vpad = ((V + 127) / 128) * 128;             // 6912
    if (rows_pad > MAX_ROWS) rows_pad = MAX_ROWS;
    if (vpad > MAX_VPAD) vpad = MAX_VPAD;

    int pb_blocks = (vpad + PB_VPB - 1) / PB_VPB;   // 216
    int fk_blocks = SB / 4;                         // 128
    prep_kernel<<<pb_blocks + fk_blocks, 256>>>(pose, J_hat, trans, T_hat,
                                                weights, B, V, vpad, SB,
                                                pb_blocks);

    dim3 grid(rows_pad / 128, vpad / 128);
    gemm_kernel<<<grid, 256>>>(out, V, B, SB);
}